// round 6
// baseline (speedup 1.0000x reference)
#include <cuda_runtime.h>
#include <cstdint>

// Problem constants
// u_t    [16,3,32,32]  f32   d_in[0]
// h_prev [16,9,128,64,64] f32 d_in[1]
// action [16,2] int32         d_in[2]
// W_u    [128,3,3,3] f32      d_in[3]
// W_h    [128,128,3,3] f32    d_in[4]
// out    [16,9,128,64,64] f32
#define WORLD 64
#define WIN   32
#define CC    128
#define BB    16
#define VV    9
#define CI_CHUNK 8

// Scratch (device globals; allocation inside kernel_launch is forbidden)
__device__ float g_Wt[9 * 128 * 128];              // [tap][ci][co]
__device__ float g_uconv[16 * 128 * 32 * 32];      // [b][co][y][x]

// ---------- packed f32x2 helpers ----------
__device__ __forceinline__ unsigned long long bcast2(float v) {
    unsigned long long r;
    unsigned int u = __float_as_uint(v);
    asm("mov.b64 %0, {%1, %2};" : "=l"(r) : "r"(u), "r"(u));
    return r;
}
__device__ __forceinline__ void ffma2(unsigned long long& a,
                                      unsigned long long w,
                                      unsigned long long b) {
    asm("fma.rn.f32x2 %0, %1, %2, %0;" : "+l"(a) : "l"(w), "l"(b));
}

// ---------- W_h transpose: [co][ci][tap] -> [tap][ci][co] ----------
__global__ void transpose_wh_kernel(const float* __restrict__ W_h) {
    int idx = blockIdx.x * blockDim.x + threadIdx.x;
    if (idx >= 9 * 128 * 128) return;
    int co  = idx & 127;
    int ci  = (idx >> 7) & 127;
    int tap = idx >> 14;
    g_Wt[idx] = W_h[(co * 128 + ci) * 9 + tap];
}

// ---------- encoder: circular conv u_t * W_u -> g_uconv ----------
__global__ void encoder_kernel(const float* __restrict__ u_t,
                               const float* __restrict__ W_u) {
    int co = blockIdx.x;
    int b  = blockIdx.y;
    __shared__ float us[3 * 32 * 32];
    __shared__ float ws[27];
    int tid = threadIdx.x;
    const float* up = u_t + (size_t)b * 3 * 1024;
    for (int e = tid; e < 3072; e += 256) us[e] = up[e];
    if (tid < 27) ws[tid] = W_u[co * 27 + tid];
    __syncthreads();

    int y  = (tid * 4) >> 5;
    int x0 = (tid * 4) & 31;
    float acc[4] = {0.f, 0.f, 0.f, 0.f};
#pragma unroll
    for (int ci = 0; ci < 3; ++ci)
#pragma unroll
        for (int ky = 0; ky < 3; ++ky) {
            int yy = (y + ky - 1 + 32) & 31;
#pragma unroll
            for (int kx = 0; kx < 3; ++kx) {
                float w = ws[ci * 9 + ky * 3 + kx];
#pragma unroll
                for (int k = 0; k < 4; ++k) {
                    int xx = (x0 + k + kx - 1 + 32) & 31;
                    acc[k] = fmaf(w, us[ci * 1024 + yy * 32 + xx], acc[k]);
                }
            }
        }
    float4 r = {acc[0], acc[1], acc[2], acc[3]};
    *(float4*)&g_uconv[((size_t)(b * 128 + co) * 32 + y) * 32 + x0] = r;
}

// ---------- main recurrent conv ----------
// Block: one (b, v), 2 output rows. Threads 256: tid = cg*32 + pxg;
// cg (0..7) selects 16 output channels; pxg -> (row_local, x0=4*xg).
// Per thread: 8 co-pairs x 4 px f32x2 accumulators.
__global__ __launch_bounds__(256)
void fernn_main_kernel(const float* __restrict__ h_prev,
                       const int* __restrict__ action,
                       float* __restrict__ out) {
    __shared__ float w_s[CI_CHUNK][9][128];   // [ci][tap][co]
    __shared__ float in_s[CI_CHUNK][4][72];   // [ci][ry][xx], xx-1 = pixel x offset

    int rt = blockIdx.x;   // 0..31 row-pair tile
    int v  = blockIdx.y;   // 0..8
    int b  = blockIdx.z;   // 0..15
    int row0 = rt * 2;

    int tid = threadIdx.x;
    int cg  = tid >> 5;          // 0..7
    int pxg = tid & 31;
    int rl  = pxg >> 4;          // 0..1
    int x0  = (pxg & 15) * 4;    // 0..60

    int ax = action[b * 2 + 0];
    int ay = action[b * 2 + 1];
    int vx = v / 3 - 1;
    int vy = v % 3 - 1;
    // reference (code, not comment!): input = h_prev[b,v,(ci-vy)%C,(y+ky-1+ay-vx)%H,(x+kx-1+ax)%W]
    int Sy = ay - vx;
    int Sx = ax;

    const float* hp = h_prev + (size_t)(b * VV + v) * CC * WORLD * WORLD;

    unsigned long long acc[8][4];
#pragma unroll
    for (int j = 0; j < 8; ++j)
#pragma unroll
        for (int k = 0; k < 4; ++k) acc[j][k] = 0ull;

#pragma unroll 1
    for (int chunk = 0; chunk < CC / CI_CHUNK; ++chunk) {
        int ci0 = chunk * CI_CHUNK;
        __syncthreads();
        // weights: w_s[ci][tap][co] <- g_Wt[tap][ci0+ci][co], vectorized, coalesced
        for (int e = tid; e < CI_CHUNK * 9 * 32; e += 256) {
            int v4 = e & 31;
            int ct = e >> 5;            // ci*9+tap
            int ci = ct / 9;
            int tap = ct - ci * 9;
            float4 val = *(const float4*)&g_Wt[((size_t)tap * 128 + (ci0 + ci)) * 128 + v4 * 4];
            *(float4*)&w_s[ci][tap][v4 * 4] = val;
        }
        // inputs: 4 rows (row0-1..row0+2 shifted), 66 columns (x=-1..64 shifted), wraps folded here
        for (int e = tid; e < CI_CHUNK * 4 * 66; e += 256) {
            int xx = e % 66;
            int t  = e / 66;
            int ry = t & 3;
            int ci = t >> 2;
            int cglob = (ci0 + ci - vy + 128) & 127;
            int gy = (row0 + ry - 1 + Sy + 64) & 63;
            int gx = (xx - 1 + Sx + 64) & 63;
            in_s[ci][ry][xx] = hp[(size_t)cglob * 4096 + gy * 64 + gx];
        }
        __syncthreads();

#pragma unroll 1
        for (int ci = 0; ci < CI_CHUNK; ++ci) {
            // broadcast input pairs: bc[dy][m] = value at xx = x0 + m (m=0..5)
            unsigned long long bc[3][6];
#pragma unroll
            for (int dy = 0; dy < 3; ++dy) {
                int ry = rl + dy;
                float4 q = *(const float4*)&in_s[ci][ry][x0];
                bc[dy][0] = bcast2(q.x);
                bc[dy][1] = bcast2(q.y);
                bc[dy][2] = bcast2(q.z);
                bc[dy][3] = bcast2(q.w);
                bc[dy][4] = bcast2(in_s[ci][ry][x0 + 4]);
                bc[dy][5] = bcast2(in_s[ci][ry][x0 + 5]);
            }
#pragma unroll
            for (int tap = 0; tap < 9; ++tap) {
                int dy = tap / 3;
                int dx = tap % 3;
                const ulonglong2* wp = (const ulonglong2*)&w_s[ci][tap][cg * 16];
                ulonglong2 wA = wp[0];
                ulonglong2 wB = wp[1];
                ulonglong2 wC = wp[2];
                ulonglong2 wD = wp[3];
#pragma unroll
                for (int k = 0; k < 4; ++k) {
                    unsigned long long bcv = bc[dy][k + dx];
                    ffma2(acc[0][k], wA.x, bcv);
                    ffma2(acc[1][k], wA.y, bcv);
                    ffma2(acc[2][k], wB.x, bcv);
                    ffma2(acc[3][k], wB.y, bcv);
                    ffma2(acc[4][k], wC.x, bcv);
                    ffma2(acc[5][k], wC.y, bcv);
                    ffma2(acc[6][k], wD.x, bcv);
                    ffma2(acc[7][k], wD.y, bcv);
                }
            }
        }
    }

    // epilogue: + u_full (top-left 32x32 window only), relu, store
    int row = row0 + rl;
    bool do_u = (row < WIN) && (x0 < WIN);
    float* op = out + (size_t)(b * VV + v) * CC * 4096 + row * 64 + x0;
    const float* ub = g_uconv + (size_t)b * CC * 1024 + row * 32 + x0;

#pragma unroll
    for (int j = 0; j < 8; ++j) {
        int co0 = cg * 16 + 2 * j;
        float lo[4], hi[4];
#pragma unroll
        for (int k = 0; k < 4; ++k) {
            unsigned int l, h;
            asm("mov.b64 {%0, %1}, %2;" : "=r"(l), "=r"(h) : "l"(acc[j][k]));
            lo[k] = __uint_as_float(l);
            hi[k] = __uint_as_float(h);
        }
        if (do_u) {
            float4 u0 = *(const float4*)&ub[(size_t)co0 * 1024];
            float4 u1 = *(const float4*)&ub[(size_t)(co0 + 1) * 1024];
            lo[0] += u0.x; lo[1] += u0.y; lo[2] += u0.z; lo[3] += u0.w;
            hi[0] += u1.x; hi[1] += u1.y; hi[2] += u1.z; hi[3] += u1.w;
        }
        float4 r0 = {fmaxf(lo[0], 0.f), fmaxf(lo[1], 0.f), fmaxf(lo[2], 0.f), fmaxf(lo[3], 0.f)};
        float4 r1 = {fmaxf(hi[0], 0.f), fmaxf(hi[1], 0.f), fmaxf(hi[2], 0.f), fmaxf(hi[3], 0.f)};
        *(float4*)&op[(size_t)co0 * 4096] = r0;
        *(float4*)&op[(size_t)(co0 + 1) * 4096] = r1;
    }
}

extern "C" void kernel_launch(void* const* d_in, const int* in_sizes, int n_in,
                              void* d_out, int out_size) {
    const float* u_t    = (const float*)d_in[0];
    const float* h_prev = (const float*)d_in[1];
    const int*   action = (const int*)d_in[2];
    const float* W_u    = (const float*)d_in[3];
    const float* W_h    = (const float*)d_in[4];
    float* out = (float*)d_out;

    transpose_wh_kernel<<<(9 * 128 * 128 + 255) / 256, 256>>>(W_h);
    encoder_kernel<<<dim3(128, 16), 256>>>(u_t, W_u);
    fernn_main_kernel<<<dim3(32, 9, 16), 256>>>(h_prev, action, out);
}

// round 8
// speedup vs baseline: 1.2286x; 1.2286x over previous
#include <cuda_runtime.h>
#include <cuda_bf16.h>
#include <cstdint>

// Problem constants
// u_t    [16,3,32,32]  f32   d_in[0]
// h_prev [16,9,128,64,64] f32 d_in[1]
// action [16,2] int32         d_in[2]
// W_u    [128,3,3,3] f32      d_in[3]
// W_h    [128,128,3,3] f32    d_in[4]
// out    [16,9,128,64,64] f32
#define WORLD 64
#define WIN   32
#define CC    128
#define VV    9
#define KP    40          // padded K stride in bf16 elems (80 B rows, ldmatrix conflict-free)

// ---- dynamic smem layout (bytes) ----
// A tiles: hi[128][KP] + lo[128][KP] bf16          = 20480
// B tiles: hi[256][KP] + lo[256][KP] bf16          = 40960
// Bext:    u32[6 rows][32 ci][66 xx] (hi|lo pack)  = 50688
#define SM_A     0
#define SM_B     20480
#define SM_BEXT  61440
#define SMEM_TOTAL (SM_BEXT + 6*32*66*4)   // 112128

// Scratch (device globals; no allocation allowed)
// g_Wsp: [chunk(4)][tap(9)][hl(2)][co(128)][kp(KP)] bf16 — exact smem A-tile image
__device__ __align__(16) unsigned short g_Wsp[4 * 9 * 2 * 128 * KP];
__device__ float g_uconv[16 * 128 * 32 * 32];   // [b][co][y][x]

// ---------------- PTX helpers ----------------
__device__ __forceinline__ uint32_t smem_u32(const void* p) {
    uint32_t a;
    asm("{ .reg .u64 t; cvta.to.shared.u64 t, %1; cvt.u32.u64 %0, t; }" : "=r"(a) : "l"(p));
    return a;
}
__device__ __forceinline__ void ldsm4(uint32_t r[4], uint32_t addr) {
    asm volatile("ldmatrix.sync.aligned.m8n8.x4.shared.b16 {%0,%1,%2,%3}, [%4];"
                 : "=r"(r[0]), "=r"(r[1]), "=r"(r[2]), "=r"(r[3]) : "r"(addr));
}
__device__ __forceinline__ void mma16816(float c[4], const uint32_t a[4], const uint32_t b[2]) {
    asm volatile(
        "mma.sync.aligned.m16n8k16.row.col.f32.bf16.bf16.f32 "
        "{%0,%1,%2,%3}, {%4,%5,%6,%7}, {%8,%9}, {%0,%1,%2,%3};"
        : "+f"(c[0]), "+f"(c[1]), "+f"(c[2]), "+f"(c[3])
        : "r"(a[0]), "r"(a[1]), "r"(a[2]), "r"(a[3]), "r"(b[0]), "r"(b[1]));
}

// ---------- prep: split W_h into bf16 hi/lo A-tile images ----------
__global__ void prep_w_kernel(const float* __restrict__ W_h) {
    int idx = blockIdx.x * blockDim.x + threadIdx.x;
    if (idx >= 4 * 9 * 128 * KP) return;
    int kp   = idx % KP;
    int co   = (idx / KP) & 127;
    int rest = idx / (KP * 128);       // 0..35
    int tap  = rest % 9;
    int chunk = rest / 9;
    float v = 0.f;
    if (kp < 32) v = W_h[((co * 128) + (chunk * 32 + kp)) * 9 + tap];
    __nv_bfloat16 bh = __float2bfloat16(v);
    float r = v - __bfloat162float(bh);
    __nv_bfloat16 bl = __float2bfloat16(r);
    int tile = chunk * 9 + tap;
    g_Wsp[((size_t)(tile * 2 + 0) * 128 + co) * KP + kp] = __bfloat16_as_ushort(bh);
    g_Wsp[((size_t)(tile * 2 + 1) * 128 + co) * KP + kp] = __bfloat16_as_ushort(bl);
}

// ---------- encoder: circular conv u_t * W_u -> g_uconv (exact f32) ----------
__global__ void encoder_kernel(const float* __restrict__ u_t,
                               const float* __restrict__ W_u) {
    int co = blockIdx.x;
    int b  = blockIdx.y;
    __shared__ float us[3 * 32 * 32];
    __shared__ float ws[27];
    int tid = threadIdx.x;
    const float* up = u_t + (size_t)b * 3 * 1024;
    for (int e = tid; e < 3072; e += 256) us[e] = up[e];
    if (tid < 27) ws[tid] = W_u[co * 27 + tid];
    __syncthreads();

    int y  = (tid * 4) >> 5;
    int x0 = (tid * 4) & 31;
    float acc[4] = {0.f, 0.f, 0.f, 0.f};
#pragma unroll
    for (int ci = 0; ci < 3; ++ci)
#pragma unroll
        for (int ky = 0; ky < 3; ++ky) {
            int yy = (y + ky - 1 + 32) & 31;
#pragma unroll
            for (int kx = 0; kx < 3; ++kx) {
                float w = ws[ci * 9 + ky * 3 + kx];
#pragma unroll
                for (int k = 0; k < 4; ++k) {
                    int xx = (x0 + k + kx - 1 + 32) & 31;
                    acc[k] = fmaf(w, us[ci * 1024 + yy * 32 + xx], acc[k]);
                }
            }
        }
    float4 r = {acc[0], acc[1], acc[2], acc[3]};
    *(float4*)&g_uconv[((size_t)(b * 128 + co) * 32 + y) * 32 + x0] = r;
}

// ---------- main: warp-MMA (HMMA) per-tap GEMM, split-bf16 3-pass ----------
// Block = (4-row tile, v, b); D[128 co][256 px] ; 8 warps: wm=wid&1 (co 64), wn=wid>>1 (row)
__global__ __launch_bounds__(256)
void fernn_hmma_kernel(const float* __restrict__ h_prev,
                       const int* __restrict__ action,
                       float* __restrict__ out) {
    extern __shared__ unsigned char smem[];
    uint32_t sb = smem_u32(smem);
    uint32_t* bext = (uint32_t*)(smem + SM_BEXT);

    int tid  = threadIdx.x;
    int wid  = tid >> 5;
    int lane = tid & 31;
    int wm = wid & 1;     // co half
    int wn = wid >> 1;    // output row within tile (0..3)

    int y0 = blockIdx.x * 4;
    int v  = blockIdx.y;
    int b  = blockIdx.z;

    int ax = action[b * 2 + 0];
    int ay = action[b * 2 + 1];
    int vx = v / 3 - 1;
    int vy = v % 3 - 1;
    // folded index (verified R2): in = h_prev[b,v,(ci-vy)%C,(y+ky-1+Sy)%H,(x+kx-1+Sx)%W]
    int Sy = ay - vx;
    int Sx = ax;
    const float* hp = h_prev + (size_t)(b * VV + v) * CC * WORLD * WORLD;

    // per-lane ldmatrix address components
    int mi = lane >> 3;          // 8-thread group id
    int li = lane & 7;
    uint32_t aBase = sb + SM_A + (uint32_t)((wm * 64 + (mi & 1) * 8 + li) * (KP * 2))
                   + (uint32_t)(((mi >> 1) * 8) * 2);
    uint32_t bBase = sb + SM_B + (uint32_t)((wn * 64 + (mi >> 1) * 8 + li) * (KP * 2))
                   + (uint32_t)(((mi & 1) * 8) * 2);

    float acc[4][8][4];
#pragma unroll
    for (int mt = 0; mt < 4; ++mt)
#pragma unroll
        for (int nt = 0; nt < 8; ++nt)
#pragma unroll
            for (int c = 0; c < 4; ++c) acc[mt][nt][c] = 0.f;

#pragma unroll 1
    for (int chunk = 0; chunk < 4; ++chunk) {
        int ci0 = chunk * 32;
        __syncthreads();
        // ---- build Bext: packed (hi|lo) bf16, [ry 0..5][ci 0..31][xx 0..65] ----
        for (int p = wid; p < 6 * 32; p += 8) {
            int ry = p >> 5;
            int ci = p & 31;
            int cglob = (ci0 + ci - vy + 128) & 127;
            int gy = (y0 - 1 + ry + Sy + 128) & 63;
            const float* rowp = hp + (size_t)cglob * 4096 + gy * 64;
            uint32_t* dst = bext + (ry * 32 + ci) * 66;
            for (int xx = lane; xx < 66; xx += 32) {
                int gx = (xx - 1 + Sx + 64) & 63;
                float val = rowp[gx];
                __nv_bfloat16 bh = __float2bfloat16(val);
                float res = val - __bfloat162float(bh);
                __nv_bfloat16 bl = __float2bfloat16(res);
                dst[xx] = (uint32_t)__bfloat16_as_ushort(bh)
                        | ((uint32_t)__bfloat16_as_ushort(bl) << 16);
            }
        }

#pragma unroll 1
        for (int t = 0; t < 9; ++t) {
            int dy = t / 3;
            int dx = t % 3;
            __syncthreads();

            // A tiles: linear copy of pre-split hi+lo (20480 B)
            {
                const float4* asrc = (const float4*)((const unsigned char*)g_Wsp
                                     + (size_t)(chunk * 9 + t) * 20480);
                float4* adst = (float4*)(smem + SM_A);
#pragma unroll
                for (int i = 0; i < 5; ++i) adst[tid + 256 * i] = asrc[tid + 256 * i];
            }
            // B tiles: [n=256][k=32] hi/lo, n=(rl,x) <- Bext[(rl+dy)][k][x+dx]
            {
                int n  = tid;
                int rl = n >> 6;
                int x  = n & 63;
                uint32_t* dh = (uint32_t*)(smem + SM_B) + n * (KP / 2);
                uint32_t* dl = (uint32_t*)(smem + SM_B + 256 * KP * 2) + n * (KP / 2);
#pragma unroll
                for (int half = 0; half < 2; ++half) {
                    const uint32_t* src = bext + (((rl + dy) * 32) + half * 16) * 66 + (x + dx);
#pragma unroll
                    for (int j = 0; j < 8; ++j) {
                        uint32_t u0 = src[(2 * j) * 66];
                        uint32_t u1 = src[(2 * j + 1) * 66];
                        dh[half * 8 + j] = (u0 & 0xFFFFu) | (u1 << 16);
                        dl[half * 8 + j] = (u0 >> 16) | (u1 & 0xFFFF0000u);
                    }
                }
            }
            __syncthreads();

            // ---- MMA: 3 passes (AhBh, AhBl, AlBh), K=32 as 2 k-steps ----
#pragma unroll
            for (int ks = 0; ks < 2; ++ks) {
                uint32_t Ah[4][4], Al[4][4];
#pragma unroll
                for (int mt = 0; mt < 4; ++mt) {
                    ldsm4(Ah[mt], aBase + mt * (16 * KP * 2) + ks * 32);
                    ldsm4(Al[mt], aBase + 128 * KP * 2 + mt * (16 * KP * 2) + ks * 32);
                }
#pragma unroll
                for (int ntp = 0; ntp < 4; ++ntp) {
                    uint32_t bh[4], bl[4];
                    ldsm4(bh, bBase + ntp * (16 * KP * 2) + ks * 32);
                    ldsm4(bl, bBase + 256 * KP * 2 + ntp * (16 * KP * 2) + ks * 32);
                    uint32_t* bh0 = &bh[0];  // tile 2*ntp   : {r0,r1}
                    uint32_t* bh1 = &bh[2];  // tile 2*ntp+1 : {r2,r3}
                    uint32_t* bl0 = &bl[0];
                    uint32_t* bl1 = &bl[2];
#pragma unroll
                    for (int mt = 0; mt < 4; ++mt) {
                        mma16816(acc[mt][2 * ntp],     Ah[mt], bh0);
                        mma16816(acc[mt][2 * ntp + 1], Ah[mt], bh1);
                        mma16816(acc[mt][2 * ntp],     Ah[mt], bl0);
                        mma16816(acc[mt][2 * ntp + 1], Ah[mt], bl1);
                        mma16816(acc[mt][2 * ntp],     Al[mt], bh0);
                        mma16816(acc[mt][2 * ntp + 1], Al[mt], bh1);
                    }
                }
            }
        }
    }

    // ---- epilogue: +u (top-left window), relu, store ----
    int row = y0 + wn;
    float* obase = out + (size_t)((b * VV + v) * CC) * 4096 + row * 64;
    const float* ubase = g_uconv + (size_t)(b * CC) * 1024 + row * 32;
    bool rowu = (row < WIN);

#pragma unroll
    for (int mt = 0; mt < 4; ++mt) {
        int co0 = wm * 64 + mt * 16 + (lane >> 2);
#pragma unroll
        for (int nt = 0; nt < 8; ++nt) {
            int x0 = nt * 8 + 2 * (lane & 3);
            float2 v0 = {acc[mt][nt][0], acc[mt][nt][1]};
            float2 v1 = {acc[mt][nt][2], acc[mt][nt][3]};
            if (rowu && x0 < WIN) {
                const float* u0 = ubase + (size_t)co0 * 1024 + x0;
                const float* u1 = ubase + (size_t)(co0 + 8) * 1024 + x0;
                v0.x += u0[0]; v0.y += u0[1];
                v1.x += u1[0]; v1.y += u1[1];
            }
            v0.x = fmaxf(v0.x, 0.f); v0.y = fmaxf(v0.y, 0.f);
            v1.x = fmaxf(v1.x, 0.f); v1.y = fmaxf(v1.y, 0.f);
            *(float2*)(obase + (size_t)co0 * 4096 + x0)       = v0;
            *(float2*)(obase + (size_t)(co0 + 8) * 4096 + x0) = v1;
        }
    }
}

extern "C" void kernel_launch(void* const* d_in, const int* in_sizes, int n_in,
                              void* d_out, int out_size) {
    const float* u_t    = (const float*)d_in[0];
    const float* h_prev = (const float*)d_in[1];
    const int*   action = (const int*)d_in[2];
    const float* W_u    = (const float*)d_in[3];
    const float* W_h    = (const float*)d_in[4];
    float* out = (float*)d_out;

    cudaFuncSetAttribute(fernn_hmma_kernel,
                         cudaFuncAttributeMaxDynamicSharedMemorySize, SMEM_TOTAL);

    prep_w_kernel<<<(4 * 9 * 128 * KP + 255) / 256, 256>>>(W_h);
    encoder_kernel<<<dim3(128, 16), 256>>>(u_t, W_u);
    fernn_hmma_kernel<<<dim3(16, 9, 16), 256, SMEM_TOTAL>>>(h_prev, action, out);
}

// round 9
// speedup vs baseline: 1.4303x; 1.1642x over previous
#include <cuda_runtime.h>
#include <cuda_bf16.h>
#include <cstdint>

// Problem constants
// u_t    [16,3,32,32]  f32   d_in[0]
// h_prev [16,9,128,64,64] f32 d_in[1]
// action [16,2] int32         d_in[2]
// W_u    [128,3,3,3] f32      d_in[3]
// W_h    [128,128,3,3] f32    d_in[4]
// out    [16,9,128,64,64] f32
#define WORLD 64
#define WIN   32
#define CC    128
#define VV    9

// ---- smem layout ----
// Pd: pixel plane, u64[ks 8][j0 4][420], rc = ry*68 + xx (ry 0..5, xx 0..65)
//     value u64 = (tf32 at k = 8*ks + j0, tf32 at k + 4)
// Wd: weight plane (double buffered), u64[ks 8][j0 4][132], idx = co
#define PD_BYTES 107520          // 8*4*420*8
#define WD_BYTES 33792           // 8*4*132*8
#define SM_W     PD_BYTES
#define SMEM_TOTAL (PD_BYTES + 2 * WD_BYTES)   // 175104

// Scratch (device globals; no allocation allowed)
__device__ __align__(16) uint32_t g_Wtf[18 * 8448];   // [chunk*9+tap] planes, smem Wd image
__device__ float g_uconv[16 * 128 * 32 * 32];         // [b][co][y][x]

// ---------------- helpers ----------------
__device__ __forceinline__ uint32_t smem_u32(const void* p) {
    uint32_t a;
    asm("{ .reg .u64 t; cvta.to.shared.u64 t, %1; cvt.u32.u64 %0, t; }" : "=r"(a) : "l"(p));
    return a;
}
__device__ __forceinline__ uint32_t f2tf32(float v) {
    uint32_t r;
    asm("cvt.rna.tf32.f32 %0, %1;" : "=r"(r) : "f"(v));
    return r;
}
__device__ __forceinline__ void lds64(uint32_t& lo, uint32_t& hi, uint32_t addr) {
    asm volatile("ld.shared.v2.b32 {%0,%1}, [%2];" : "=r"(lo), "=r"(hi) : "r"(addr));
}
__device__ __forceinline__ void mma_tf32(float c[4], const uint32_t a[4], const uint32_t b[2]) {
    asm volatile(
        "mma.sync.aligned.m16n8k8.row.col.f32.tf32.tf32.f32 "
        "{%0,%1,%2,%3}, {%4,%5,%6,%7}, {%8,%9}, {%0,%1,%2,%3};"
        : "+f"(c[0]), "+f"(c[1]), "+f"(c[2]), "+f"(c[3])
        : "r"(a[0]), "r"(a[1]), "r"(a[2]), "r"(a[3]), "r"(b[0]), "r"(b[1]));
}

// ---------- prep: W_h -> tf32 weight planes (smem Wd images) ----------
__global__ void prep_w_kernel(const float* __restrict__ W_h) {
    int idx = blockIdx.x * blockDim.x + threadIdx.x;
    if (idx >= 2 * 9 * 64 * 128) return;
    int co   = idx & 127;
    int k    = (idx >> 7) & 63;
    int rest = idx >> 13;                 // plane = chunk*9 + tap
    int tap   = rest % 9;
    int chunk = rest / 9;
    float v = W_h[((size_t)co * 128 + chunk * 64 + k) * 9 + tap];
    uint32_t u = f2tf32(v);
    g_Wtf[(size_t)rest * 8448 + ((((k >> 3) * 4 + (k & 3)) * 132 + co) * 2 + ((k >> 2) & 1))] = u;
}

// ---------- encoder: circular conv u_t * W_u -> g_uconv (exact f32) ----------
__global__ void encoder_kernel(const float* __restrict__ u_t,
                               const float* __restrict__ W_u) {
    int co = blockIdx.x;
    int b  = blockIdx.y;
    __shared__ float us[3 * 32 * 32];
    __shared__ float ws[27];
    int tid = threadIdx.x;
    const float* up = u_t + (size_t)b * 3 * 1024;
    for (int e = tid; e < 3072; e += 256) us[e] = up[e];
    if (tid < 27) ws[tid] = W_u[co * 27 + tid];
    __syncthreads();

    int y  = (tid * 4) >> 5;
    int x0 = (tid * 4) & 31;
    float acc[4] = {0.f, 0.f, 0.f, 0.f};
#pragma unroll
    for (int ci = 0; ci < 3; ++ci)
#pragma unroll
        for (int ky = 0; ky < 3; ++ky) {
            int yy = (y + ky - 1 + 32) & 31;
#pragma unroll
            for (int kx = 0; kx < 3; ++kx) {
                float w = ws[ci * 9 + ky * 3 + kx];
#pragma unroll
                for (int k = 0; k < 4; ++k) {
                    int xx = (x0 + k + kx - 1 + 32) & 31;
                    acc[k] = fmaf(w, us[ci * 1024 + yy * 32 + xx], acc[k]);
                }
            }
        }
    float4 r = {acc[0], acc[1], acc[2], acc[3]};
    *(float4*)&g_uconv[((size_t)(b * 128 + co) * 32 + y) * 32 + x0] = r;
}

// ---------- main: tf32 warp-MMA, single pixel plane per chunk, per-tap addr shifts ----------
// Block = (4-row tile, v, b); D[co=128][px=256]; 8 warps: wco = wid&1 (64 co), rl = wid>>1 (row)
__global__ __launch_bounds__(256, 1)
void fernn_tf32_kernel(const float* __restrict__ h_prev,
                       const int* __restrict__ action,
                       float* __restrict__ out) {
    extern __shared__ unsigned char smem[];
    uint32_t sb = smem_u32(smem);
    uint32_t* P32 = (uint32_t*)smem;

    int tid  = threadIdx.x;
    int wid  = tid >> 5;
    int lane = tid & 31;
    int wco = wid & 1;
    int rl  = wid >> 1;          // 0..3
    int j0  = lane & 3;
    int lq  = lane >> 2;         // 0..7

    int y0 = blockIdx.x * 4;
    int v  = blockIdx.y;
    int b  = blockIdx.z;

    int ax = action[b * 2 + 0];
    int ay = action[b * 2 + 1];
    int vx = v / 3 - 1;
    int vy = v % 3 - 1;
    // folded index (verified R2): in = h_prev[b,v,(ci-vy)%C,(y+ky-1+Sy)%H,(x+kx-1+Sx)%W]
    int Sy = ay - vx;
    int Sx = ax;
    const float* hp = h_prev + (size_t)(b * VV + v) * CC * WORLD * WORLD;

    float acc[4][8][4];
#pragma unroll
    for (int mt = 0; mt < 4; ++mt)
#pragma unroll
        for (int nt = 0; nt < 8; ++nt)
#pragma unroll
            for (int c = 0; c < 4; ++c) acc[mt][nt][c] = 0.f;

#pragma unroll 1
    for (int chunk = 0; chunk < 2; ++chunk) {
        int ci0 = chunk * 64;
        __syncthreads();   // previous chunk's MMAs done before P overwrite
        // ---- build pixel plane P (once per chunk): 384 rows of 66 ----
#pragma unroll 1
        for (int r = wid; r < 384; r += 8) {
            int k  = r / 6;
            int ry = r % 6;
            int cglob = (ci0 + k - vy + 128) & 127;
            int gy = (y0 - 1 + ry + Sy + 128) & 63;
            const float* rowp = hp + (size_t)cglob * 4096 + gy * 64;
            uint32_t* dst = P32 + ((((k >> 3) * 4 + (k & 3)) * 420 + ry * 68) * 2 + ((k >> 2) & 1));
            for (int xx = lane; xx < 66; xx += 32) {
                int gx = (xx - 1 + Sx + 64) & 63;
                dst[xx * 2] = f2tf32(rowp[gx]);
            }
        }
        if (chunk == 0) {
            // preload W plane 0 into buffer 0
            const float4* wsrc = (const float4*)g_Wtf;
            float4* wdst = (float4*)(smem + SM_W);
#pragma unroll
            for (int e = 0; e < 9; ++e) {
                int i = tid + e * 256;
                if (i < 2112) wdst[i] = wsrc[i];
            }
        }
        __syncthreads();

#pragma unroll 1
        for (int t = 0; t < 9; ++t) {
            int s  = chunk * 9 + t;
            int dy = t / 3;
            int dx = t % 3;

            // prefetch next W plane into the other buffer (overlaps with MMAs below)
            if (s < 17) {
                const float4* wsrc = (const float4*)((const unsigned char*)g_Wtf
                                      + (size_t)(s + 1) * WD_BYTES);
                float4* wdst = (float4*)(smem + SM_W + (size_t)((s + 1) & 1) * WD_BYTES);
#pragma unroll
                for (int e = 0; e < 9; ++e) {
                    int i = tid + e * 256;
                    if (i < 2112) wdst[i] = wsrc[i];
                }
            }

            uint32_t wcur = sb + SM_W + (uint32_t)((s & 1) * WD_BYTES);
            uint32_t brow = sb + (uint32_t)(((rl + dy) * 68 + lq + dx) * 8);

#pragma unroll
            for (int ks = 0; ks < 8; ++ks) {
                uint32_t A[4][4];
                uint32_t abase = wcur + (uint32_t)(((ks * 4 + j0) * 132) * 8);
#pragma unroll
                for (int mt = 0; mt < 4; ++mt) {
                    int co = wco * 64 + mt * 16 + lq;
                    lds64(A[mt][0], A[mt][2], abase + co * 8);
                    lds64(A[mt][1], A[mt][3], abase + (co + 8) * 8);
                }
                uint32_t bbase = brow + (uint32_t)(((ks * 4 + j0) * 420) * 8);
#pragma unroll
                for (int nt = 0; nt < 8; ++nt) {
                    uint32_t Bf[2];
                    lds64(Bf[0], Bf[1], bbase + nt * 64);
#pragma unroll
                    for (int mt = 0; mt < 4; ++mt) mma_tf32(acc[mt][nt], A[mt], Bf);
                }
            }
            __syncthreads();
        }
    }

    // ---- epilogue: +u (top-left window), relu, store ----
    int y = y0 + rl;
    float* obase = out + (size_t)((b * VV + v) * CC) * 4096 + (size_t)y * 64;
    bool rowu = (y < WIN);

#pragma unroll
    for (int mt = 0; mt < 4; ++mt) {
        int co = wco * 64 + mt * 16 + lq;
#pragma unroll
        for (int nt = 0; nt < 8; ++nt) {
            int px = nt * 8 + 2 * j0;
            float2 v0 = {acc[mt][nt][0], acc[mt][nt][1]};
            float2 v1 = {acc[mt][nt][2], acc[mt][nt][3]};
            if (rowu && px < WIN) {
                const float* u0 = g_uconv + (size_t)(b * CC + co) * 1024 + y * 32 + px;
                const float* u1 = g_uconv + (size_t)(b * CC + co + 8) * 1024 + y * 32 + px;
                v0.x += u0[0]; v0.y += u0[1];
                v1.x += u1[0]; v1.y += u1[1];
            }
            v0.x = fmaxf(v0.x, 0.f); v0.y = fmaxf(v0.y, 0.f);
            v1.x = fmaxf(v1.x, 0.f); v1.y = fmaxf(v1.y, 0.f);
            *(float2*)(obase + (size_t)co * 4096 + px)       = v0;
            *(float2*)(obase + (size_t)(co + 8) * 4096 + px) = v1;
        }
    }
}

extern "C" void kernel_launch(void* const* d_in, const int* in_sizes, int n_in,
                              void* d_out, int out_size) {
    const float* u_t    = (const float*)d_in[0];
    const float* h_prev = (const float*)d_in[1];
    const int*   action = (const int*)d_in[2];
    const float* W_u    = (const float*)d_in[3];
    const float* W_h    = (const float*)d_in[4];
    float* out = (float*)d_out;

    cudaFuncSetAttribute(fernn_tf32_kernel,
                         cudaFuncAttributeMaxDynamicSharedMemorySize, SMEM_TOTAL);

    prep_w_kernel<<<(2 * 9 * 64 * 128 + 255) / 256, 256>>>(W_h);
    encoder_kernel<<<dim3(128, 16), 256>>>(u_t, W_u);
    fernn_tf32_kernel<<<dim3(16, 9, 16), 256, SMEM_TOTAL>>>(h_prev, action, out);
}

// round 10
// speedup vs baseline: 2.9319x; 2.0499x over previous
#include <cuda_runtime.h>
#include <cuda_fp16.h>
#include <cstdint>

// Problem constants
// u_t    [16,3,32,32]  f32   d_in[0]
// h_prev [16,9,128,64,64] f32 d_in[1]
// action [16,2] int32         d_in[2]
// W_u    [128,3,3,3] f32      d_in[3]
// W_h    [128,128,3,3] f32    d_in[4]
// out    [16,9,128,64,64] f32
#define WORLD 64
#define WIN   32
#define CC    128
#define VV    9

// ---- smem layout (per CTA, dynamic) ----
// P64: pixel plane u64[16 slices][276]  (slice = ks*4+kq; row rc = ry*68+xx, ry 0..3, xx 0..65)
//      u64 = (u32 half2 at ci-pair p = 8ks+kq, u32 half2 at p+4); half2 = (ci=2p, ci=2p+1)
// W64: weight plane (double buffered) u64[16 slices][132] (idx = co)
#define PD_BYTES (16*276*8)              // 35328
#define SM_W     PD_BYTES
#define WD_BYTES (16*132*8)              // 16896
#define SMEM_TOTAL (PD_BYTES + 2*WD_BYTES)   // 69120  (x2 CTAs = 138KB/SM)

// Scratch (device globals; no allocation allowed)
__device__ __align__(16) uint32_t g_W32[18 * 4224];   // [plane=chunk*9+tap] smem W64 images
__device__ float g_uconv[16 * 128 * 32 * 32];         // [b][co][y][x]

// ---------------- helpers ----------------
__device__ __forceinline__ uint32_t smem_u32(const void* p) {
    uint32_t a;
    asm("{ .reg .u64 t; cvta.to.shared.u64 t, %1; cvt.u32.u64 %0, t; }" : "=r"(a) : "l"(p));
    return a;
}
__device__ __forceinline__ void lds64(uint32_t& lo, uint32_t& hi, uint32_t addr) {
    asm volatile("ld.shared.v2.b32 {%0,%1}, [%2];" : "=r"(lo), "=r"(hi) : "r"(addr));
}
__device__ __forceinline__ void mma_f16(float c[4], const uint32_t a[4], const uint32_t b[2]) {
    asm volatile(
        "mma.sync.aligned.m16n8k16.row.col.f32.f16.f16.f32 "
        "{%0,%1,%2,%3}, {%4,%5,%6,%7}, {%8,%9}, {%0,%1,%2,%3};"
        : "+f"(c[0]), "+f"(c[1]), "+f"(c[2]), "+f"(c[3])
        : "r"(a[0]), "r"(a[1]), "r"(a[2]), "r"(a[3]), "r"(b[0]), "r"(b[1]));
}

// ---------- prep: W_h -> fp16 weight planes (smem W64 images) ----------
__global__ void prep_w_kernel(const float* __restrict__ W_h) {
    int idx = blockIdx.x * blockDim.x + threadIdx.x;
    if (idx >= 18 * 16 * 128 * 2) return;
    int co    = idx & 127;
    int hi    = (idx >> 7) & 1;
    int s     = (idx >> 8) & 15;
    int plane = idx >> 12;            // 0..17 = chunk*9+tap
    int tap   = plane % 9;
    int chunk = plane / 9;
    int ks = s >> 2, kq = s & 3;
    int ci = chunk * 64 + ks * 16 + 2 * kq + hi * 8;
    float v0 = W_h[((size_t)co * 128 + ci) * 9 + tap];
    float v1 = W_h[((size_t)co * 128 + ci + 1) * 9 + tap];
    __half2 h = __floats2half2_rn(v0, v1);
    g_W32[(size_t)plane * 4224 + ((s * 132 + co) * 2 + hi)] = *(uint32_t*)&h;
}

// ---------- encoder: circular conv u_t * W_u -> g_uconv (exact f32) ----------
__global__ void encoder_kernel(const float* __restrict__ u_t,
                               const float* __restrict__ W_u) {
    int co = blockIdx.x;
    int b  = blockIdx.y;
    __shared__ float us[3 * 32 * 32];
    __shared__ float ws[27];
    int tid = threadIdx.x;
    const float* up = u_t + (size_t)b * 3 * 1024;
    for (int e = tid; e < 3072; e += 256) us[e] = up[e];
    if (tid < 27) ws[tid] = W_u[co * 27 + tid];
    __syncthreads();

    int y  = (tid * 4) >> 5;
    int x0 = (tid * 4) & 31;
    float acc[4] = {0.f, 0.f, 0.f, 0.f};
#pragma unroll
    for (int ci = 0; ci < 3; ++ci)
#pragma unroll
        for (int ky = 0; ky < 3; ++ky) {
            int yy = (y + ky - 1 + 32) & 31;
#pragma unroll
            for (int kx = 0; kx < 3; ++kx) {
                float w = ws[ci * 9 + ky * 3 + kx];
#pragma unroll
                for (int k = 0; k < 4; ++k) {
                    int xx = (x0 + k + kx - 1 + 32) & 31;
                    acc[k] = fmaf(w, us[ci * 1024 + yy * 32 + xx], acc[k]);
                }
            }
        }
    float4 r = {acc[0], acc[1], acc[2], acc[3]};
    *(float4*)&g_uconv[((size_t)(b * 128 + co) * 32 + y) * 32 + x0] = r;
}

// ---------- main: single-pass fp16 m16n8k16, per-tap address shifts ----------
// Block = (2-row tile, v, b); D[co=128][px=128]; 8 warps: wco=wid&1, wpx=wid>>1
// warp tile m64 n32; 2 CTAs/SM.
__global__ __launch_bounds__(256, 2)
void fernn_f16_kernel(const float* __restrict__ h_prev,
                      const int* __restrict__ action,
                      float* __restrict__ out) {
    extern __shared__ unsigned char smem[];
    uint32_t sb = smem_u32(smem);
    uint32_t* P32 = (uint32_t*)smem;

    int tid  = threadIdx.x;
    int wid  = tid >> 5;
    int lane = tid & 31;
    int wco = wid & 1;            // co half (64)
    int wpx = wid >> 1;           // 0..3
    int rl  = wpx >> 1;           // output row in tile (0..1)
    int xh  = wpx & 1;            // x half (32 px)
    int kq  = lane & 3;
    int lq  = lane >> 2;          // 0..7

    int y0 = blockIdx.x * 2;
    int v  = blockIdx.y;
    int b  = blockIdx.z;

    int ax = action[b * 2 + 0];
    int ay = action[b * 2 + 1];
    int vx = v / 3 - 1;
    int vy = v % 3 - 1;
    // folded index (verified R2): in = h_prev[b,v,(ci-vy)%C,(y+ky-1+Sy)%H,(x+kx-1+Sx)%W]
    int Sy = ay - vx;
    int Sx = ax;
    const float* hp = h_prev + (size_t)(b * VV + v) * CC * WORLD * WORLD;

    float acc[4][4][4];
#pragma unroll
    for (int mt = 0; mt < 4; ++mt)
#pragma unroll
        for (int nt = 0; nt < 4; ++nt)
#pragma unroll
            for (int c = 0; c < 4; ++c) acc[mt][nt][c] = 0.f;

#pragma unroll 1
    for (int chunk = 0; chunk < 2; ++chunk) {
        __syncthreads();   // previous taps' reads done before P overwrite
        // ---- build P (once per chunk): 128 (p,ry) rows x 66 columns of half2 ----
#pragma unroll 1
        for (int e = tid; e < 128 * 66; e += 256) {
            int r  = e / 66;
            int xx = e - r * 66;
            int p  = r >> 2;          // ci pair 0..31
            int ry = r & 3;
            int ks = p >> 3, rem = p & 7;
            int kq2 = rem & 3, hi = rem >> 2;
            int ciK = chunk * 64 + 2 * p;
            int c0 = (ciK - vy + 128) & 127;
            int c1 = (ciK + 1 - vy + 128) & 127;
            int gy = (y0 - 1 + ry + Sy + 128) & 63;
            int gx = (xx - 1 + Sx + 64) & 63;
            float f0 = hp[(size_t)c0 * 4096 + gy * 64 + gx];
            float f1 = hp[(size_t)c1 * 4096 + gy * 64 + gx];
            __half2 h = __floats2half2_rn(f0, f1);
            P32[((ks * 4 + kq2) * 276 + ry * 68 + xx) * 2 + hi] = *(uint32_t*)&h;
        }
        if (chunk == 0) {
            // preload W plane 0 into buffer 0
            const float4* wsrc = (const float4*)g_W32;
            float4* wdst = (float4*)(smem + SM_W);
            for (int i = tid; i < 1056; i += 256) wdst[i] = wsrc[i];
        }
        __syncthreads();

#pragma unroll 1
        for (int t = 0; t < 9; ++t) {
            int s  = chunk * 9 + t;
            int dy = t / 3;
            int dx = t % 3;

            // prefetch next W plane into alternate buffer (overlaps with MMAs)
            if (s < 17) {
                const float4* wsrc = (const float4*)(g_W32 + (size_t)(s + 1) * 4224);
                float4* wdst = (float4*)(smem + SM_W + (size_t)((s + 1) & 1) * WD_BYTES);
                for (int i = tid; i < 1056; i += 256) wdst[i] = wsrc[i];
            }

            uint32_t wbase = sb + SM_W + (uint32_t)((s & 1) * WD_BYTES);
            // B row base: slice sl=ks*4+kq, row (rl+dy), column (px + dx), px = xh*32+nt*8+lq
            uint32_t bb = sb + (uint32_t)(((rl + dy) * 68 + xh * 32 + lq + dx) * 8);

#pragma unroll
            for (int ks = 0; ks < 4; ++ks) {
                int sl = ks * 4 + kq;
                uint32_t A[4][4];
                uint32_t ab = wbase + (uint32_t)((sl * 132) * 8);
#pragma unroll
                for (int mt = 0; mt < 4; ++mt) {
                    int co = wco * 64 + mt * 16 + lq;
                    lds64(A[mt][0], A[mt][2], ab + co * 8);
                    lds64(A[mt][1], A[mt][3], ab + (co + 8) * 8);
                }
                uint32_t bbs = bb + (uint32_t)((sl * 276) * 8);
#pragma unroll
                for (int nt = 0; nt < 4; ++nt) {
                    uint32_t B[2];
                    lds64(B[0], B[1], bbs + nt * 64);
#pragma unroll
                    for (int mt = 0; mt < 4; ++mt) mma_f16(acc[mt][nt], A[mt], B);
                }
            }
            __syncthreads();
        }
    }

    // ---- epilogue: +u (top-left window), relu, store ----
    int y = y0 + rl;
    float* obase = out + (size_t)((b * VV + v) * CC) * 4096 + (size_t)y * 64;
    bool rowu = (y < WIN);

#pragma unroll
    for (int mt = 0; mt < 4; ++mt) {
        int co = wco * 64 + mt * 16 + lq;
#pragma unroll
        for (int nt = 0; nt < 4; ++nt) {
            int px = xh * 32 + nt * 8 + 2 * kq;
            float2 v0 = {acc[mt][nt][0], acc[mt][nt][1]};
            float2 v1 = {acc[mt][nt][2], acc[mt][nt][3]};
            if (rowu && px < WIN) {
                const float* u0 = g_uconv + (size_t)(b * CC + co) * 1024 + y * 32 + px;
                const float* u1 = g_uconv + (size_t)(b * CC + co + 8) * 1024 + y * 32 + px;
                v0.x += u0[0]; v0.y += u0[1];
                v1.x += u1[0]; v1.y += u1[1];
            }
            v0.x = fmaxf(v0.x, 0.f); v0.y = fmaxf(v0.y, 0.f);
            v1.x = fmaxf(v1.x, 0.f); v1.y = fmaxf(v1.y, 0.f);
            *(float2*)(obase + (size_t)co * 4096 + px)       = v0;
            *(float2*)(obase + (size_t)(co + 8) * 4096 + px) = v1;
        }
    }
}

extern "C" void kernel_launch(void* const* d_in, const int* in_sizes, int n_in,
                              void* d_out, int out_size) {
    const float* u_t    = (const float*)d_in[0];
    const float* h_prev = (const float*)d_in[1];
    const int*   action = (const int*)d_in[2];
    const float* W_u    = (const float*)d_in[3];
    const float* W_h    = (const float*)d_in[4];
    float* out = (float*)d_out;

    cudaFuncSetAttribute(fernn_f16_kernel,
                         cudaFuncAttributeMaxDynamicSharedMemorySize, SMEM_TOTAL);

    prep_w_kernel<<<(18 * 16 * 128 * 2 + 255) / 256, 256>>>(W_h);
    encoder_kernel<<<dim3(128, 16), 256>>>(u_t, W_u);
    fernn_f16_kernel<<<dim3(32, 9, 16), 256, SMEM_TOTAL>>>(h_prev, action, out);
}